// round 8
// baseline (speedup 1.0000x reference)
#include <cuda_runtime.h>
#include <cstddef>

// Problem constants
#define NN    16
#define DIM   32
#define FEAT  192
#define KTOT  (DIM*FEAT)      // 6144
#define YSZ   (NN*DIM*FEAT)   // 98304

// Einsum tiling
#define CPC    2               // c's per CTA (A folded into W scalar)
#define NCG    (FEAT/CPC)      // 96 c-groups
#define KSPLIT 8
#define KCTA   (KTOT/KSPLIT)   // 768
#define NST    (KCTA/32)       // 24 stages of 32 k's
#define WTILE  (32*CPC*DIM)    // 2048 floats = 8KB per stage
#define PDEPTH 4               // W ring buffer depth

// Scratch (no allocations allowed -> device globals)
__device__ float g_ybuf[YSZ];
__device__ float g_h1[YSZ];
__device__ float g_h2[YSZ];

__device__ __forceinline__ void cp16(void* dst, const void* src) {
    unsigned u = (unsigned)__cvta_generic_to_shared(dst);
    asm volatile("cp.async.cg.shared.global [%0], [%1], 16;\n" :: "r"(u), "l"(src));
}
#define CP_COMMIT() asm volatile("cp.async.commit_group;\n" ::: "memory")
#define CP_WAIT2()  asm volatile("cp.async.wait_group 2;\n" ::: "memory")

// ---------------------------------------------------------------------------
// Fused weighted einsum, 4-deep cp.async W ring, ONE barrier per stage:
//   Y[n, m, c] += sum_k H0[n,k] * A0[k%192, c] * W[k, c, m]   (+ H1/A1 stream)
// W viewed as [KTOT][FEAT][DIM]. Per 32-k stage: 8KB W tile W[32k][2c][32m]
// via cp.async (ring of 4, prefetch distance ~2.5 stages); 2KB h tile via a
// register pipeline one stage ahead (LDG+STS does the [k][n] transpose).
// Warp w computes kk = w*8..w*8+7, all 16 n, 2 c:
//   per kk = 2 LDS.32 (W) + 4 LDS.128 (h bcast) + 2 FMUL + 16 fma.rn.f32x2.
// ---------------------------------------------------------------------------
template<bool TWO_H, int MINB>
__global__ void __launch_bounds__(128, MINB)
einsum_kernel(const float* __restrict__ W,
              const float* __restrict__ H0, const float* __restrict__ A0,
              const float* __restrict__ H1, const float* __restrict__ A1,
              float* __restrict__ Y)
{
    const int ks   = blockIdx.x;           // 0..KSPLIT-1
    const int c0   = blockIdx.y * CPC;     // 0..191 step 2
    const int tid  = threadIdx.x;
    const int w    = tid >> 5;
    const int lane = tid & 31;

    __shared__ __align__(16) float  smw[PDEPTH][WTILE];       // 32KB ring
    __shared__ __align__(16) float2 shh[2][32][8];            // h stream0, 4KB
    __shared__ __align__(16) float2 shh2[TWO_H ? 2*32*8 : 8]; // h stream1
    __shared__ float sh_a0[CPC][FEAT];
    __shared__ float sh_a1[TWO_H ? CPC * FEAT : 1];

    // Stage A columns for this CTA's 2 c's.
    for (int i = tid; i < CPC * FEAT; i += 128) {
        const int cc = i / FEAT, f = i - cc * FEAT;
        sh_a0[cc][f] = A0[f * FEAT + c0 + cc];
        if (TWO_H) sh_a1[cc * FEAT + f] = A1[f * FEAT + c0 + cc];
    }

    const int kbase = ks * KCTA;
    const int kk_h  = tid >> 2;            // 0..31 : k-row this thread stages
    const int q     = tid & 3;             // n-quad

    // W tile copy: 512 16B chunks, 4 per thread, 256B contiguous per k-row.
    auto copy_w = [&](int buf, int st) {
        const int kb = kbase + st * 32;
#pragma unroll
        for (int j = 0; j < 4; ++j) {
            const int ch  = j * 128 + tid;
            const int k   = ch >> 4;
            const int off = ch & 15;
            cp16(&smw[buf][k * 64 + off * 4],
                 W + ((size_t)(kb + k) * FEAT + c0) * DIM + off * 4);
        }
    };

    float hv[4], hv2[4];
    auto load_h = [&](int st) {
        const float* hp = H0 + kbase + st * 32 + kk_h;
#pragma unroll
        for (int j = 0; j < 4; ++j) hv[j] = hp[(4 * q + j) * KTOT];
        if (TWO_H) {
            const float* hq = H1 + kbase + st * 32 + kk_h;
#pragma unroll
            for (int j = 0; j < 4; ++j) hv2[j] = hq[(4 * q + j) * KTOT];
        }
    };
    auto store_h = [&](int buf) {
        *reinterpret_cast<float4*>(&shh[buf][kk_h][2 * q]) =
            make_float4(hv[0], hv[1], hv[2], hv[3]);
        if (TWO_H)
            *reinterpret_cast<float4*>(
                &shh2[(buf * 32 + kk_h) * 8 + 2 * q]) =
                make_float4(hv2[0], hv2[1], hv2[2], hv2[3]);
    };

    unsigned long long acc[CPC][8];
#pragma unroll
    for (int cc = 0; cc < CPC; ++cc)
#pragma unroll
        for (int p = 0; p < 8; ++p) acc[cc][p] = 0ull;

    // ---- pipeline prologue: 3 W stages in flight, h[0] staged ----
    copy_w(0, 0); CP_COMMIT();
    copy_w(1, 1); CP_COMMIT();
    copy_w(2, 2); CP_COMMIT();
    load_h(0);
    store_h(0);

    const int kk0 = w * 8;

    for (int s = 0; s < NST; ++s) {
        CP_WAIT2();                          // W[s] locally complete
        __syncthreads();                     // W[s]+h[s] visible; bufs freed

        if (s + 3 < NST) copy_w((s + 3) & 3, s + 3);
        CP_COMMIT();                         // (possibly empty) keeps counts
        if (s + 1 < NST) load_h(s + 1);      // LDG issue, overlaps compute

        const int   fb   = (kbase + s * 32) % FEAT;
        const float* wcur = &smw[s & 3][0];

#pragma unroll
        for (int i = 0; i < 8; ++i) {
            const int kk = kk0 + i;
            const float* wrow = wcur + kk * 64 + lane;
            const float wr0 = wrow[0], wr1 = wrow[32];
            const float wr[CPC] = {wr0, wr1};
            const ulonglong2* hr =
                reinterpret_cast<const ulonglong2*>(&shh[s & 1][kk][0]);
            const ulonglong2 h0 = hr[0], h1 = hr[1], h2 = hr[2], h3 = hr[3];
            ulonglong2 g0, g1, g2, g3;
            if (TWO_H) {
                const ulonglong2* gr = reinterpret_cast<const ulonglong2*>(
                    &shh2[((s & 1) * 32 + kk) * 8]);
                g0 = gr[0]; g1 = gr[1]; g2 = gr[2]; g3 = gr[3];
            }
#pragma unroll
            for (int cc = 0; cc < CPC; ++cc) {
                {
                    const float wv = wr[cc] * sh_a0[cc][fb + kk];
                    unsigned long long wd;
                    asm("mov.b64 %0, {%1, %1};" : "=l"(wd) : "f"(wv));
                    asm("fma.rn.f32x2 %0, %1, %2, %0;" : "+l"(acc[cc][0]) : "l"(h0.x), "l"(wd));
                    asm("fma.rn.f32x2 %0, %1, %2, %0;" : "+l"(acc[cc][1]) : "l"(h0.y), "l"(wd));
                    asm("fma.rn.f32x2 %0, %1, %2, %0;" : "+l"(acc[cc][2]) : "l"(h1.x), "l"(wd));
                    asm("fma.rn.f32x2 %0, %1, %2, %0;" : "+l"(acc[cc][3]) : "l"(h1.y), "l"(wd));
                    asm("fma.rn.f32x2 %0, %1, %2, %0;" : "+l"(acc[cc][4]) : "l"(h2.x), "l"(wd));
                    asm("fma.rn.f32x2 %0, %1, %2, %0;" : "+l"(acc[cc][5]) : "l"(h2.y), "l"(wd));
                    asm("fma.rn.f32x2 %0, %1, %2, %0;" : "+l"(acc[cc][6]) : "l"(h3.x), "l"(wd));
                    asm("fma.rn.f32x2 %0, %1, %2, %0;" : "+l"(acc[cc][7]) : "l"(h3.y), "l"(wd));
                }
                if (TWO_H) {
                    const float wv1 = wr[cc] * sh_a1[cc * FEAT + fb + kk];
                    unsigned long long wd1;
                    asm("mov.b64 %0, {%1, %1};" : "=l"(wd1) : "f"(wv1));
                    asm("fma.rn.f32x2 %0, %1, %2, %0;" : "+l"(acc[cc][0]) : "l"(g0.x), "l"(wd1));
                    asm("fma.rn.f32x2 %0, %1, %2, %0;" : "+l"(acc[cc][1]) : "l"(g0.y), "l"(wd1));
                    asm("fma.rn.f32x2 %0, %1, %2, %0;" : "+l"(acc[cc][2]) : "l"(g1.x), "l"(wd1));
                    asm("fma.rn.f32x2 %0, %1, %2, %0;" : "+l"(acc[cc][3]) : "l"(g1.y), "l"(wd1));
                    asm("fma.rn.f32x2 %0, %1, %2, %0;" : "+l"(acc[cc][4]) : "l"(g2.x), "l"(wd1));
                    asm("fma.rn.f32x2 %0, %1, %2, %0;" : "+l"(acc[cc][5]) : "l"(g2.y), "l"(wd1));
                    asm("fma.rn.f32x2 %0, %1, %2, %0;" : "+l"(acc[cc][6]) : "l"(g3.x), "l"(wd1));
                    asm("fma.rn.f32x2 %0, %1, %2, %0;" : "+l"(acc[cc][7]) : "l"(g3.y), "l"(wd1));
                }
            }
        }

        if (s + 1 < NST) store_h((s + 1) & 1);
    }

    // ---- cross-warp reduction (W ring reused), then atomics ----
    __syncthreads();
    unsigned long long* sred = reinterpret_cast<unsigned long long*>(smw);
#pragma unroll
    for (int cc = 0; cc < CPC; ++cc)
#pragma unroll
        for (int p = 0; p < 8; ++p)
            sred[w * 512 + cc * 256 + p * 32 + lane] = acc[cc][p];
    __syncthreads();

#pragma unroll
    for (int r = 0; r < 4; ++r) {
        const int idx = tid + r * 128;     // (cc, p, m) in [0, 512)
        const unsigned long long v0 = sred[idx];
        const unsigned long long v1 = sred[idx + 512];
        const unsigned long long v2 = sred[idx + 1024];
        const unsigned long long v3 = sred[idx + 1536];
        unsigned long long s01, s23, sm;
        asm("add.rn.f32x2 %0, %1, %2;" : "=l"(s01) : "l"(v0), "l"(v1));
        asm("add.rn.f32x2 %0, %1, %2;" : "=l"(s23) : "l"(v2), "l"(v3));
        asm("add.rn.f32x2 %0, %1, %2;" : "=l"(sm)  : "l"(s01), "l"(s23));
        float lo, hi;
        asm("mov.b64 {%0, %1}, %2;" : "=f"(lo), "=f"(hi) : "l"(sm));
        const int cc = idx >> 8, p = (idx >> 5) & 7, m = idx & 31;
        float* yp = Y + ((size_t)(2 * p) * DIM + m) * FEAT + c0 + cc;
        atomicAdd(yp,                      lo);
        atomicAdd(yp + (size_t)DIM * FEAT, hi);
    }
}

// ---------------------------------------------------------------------------
// Plain transition matmul: Y[row, c] = sum_f H[row, f] * M[f, c]
// Overwrites Y (initializes the layer accumulator); einsum atomicAdds on top.
// ---------------------------------------------------------------------------
__global__ void matmul_kernel(const float* __restrict__ H,
                              const float* __restrict__ M,
                              float* __restrict__ Y)
{
    __shared__ float sh[FEAT];
    const int row = blockIdx.x;
    const int t   = threadIdx.x;
    sh[t] = H[row * FEAT + t];
    __syncthreads();
    float s0 = 0.f, s1 = 0.f, s2 = 0.f, s3 = 0.f;
#pragma unroll 8
    for (int f = 0; f < FEAT; f += 4) {
        s0 = fmaf(sh[f    ], M[(f    ) * FEAT + t], s0);
        s1 = fmaf(sh[f + 1], M[(f + 1) * FEAT + t], s1);
        s2 = fmaf(sh[f + 2], M[(f + 2) * FEAT + t], s2);
        s3 = fmaf(sh[f + 3], M[(f + 3) * FEAT + t], s3);
    }
    Y[row * FEAT + t] = (s0 + s1) + (s2 + s3);
}

// ---------------------------------------------------------------------------
// LayerNorm over last two dims (6144 per n), eps=1e-5, no affine.
// (mean-over-terms division skipped: LN is scale-invariant)
// ---------------------------------------------------------------------------
__global__ void ln_kernel(const float* __restrict__ Y, float* __restrict__ O)
{
    const int n = blockIdx.x;
    const int t = threadIdx.x;
    const float* y = Y + (size_t)n * KTOT;

    float s = 0.f, q = 0.f;
    for (int i = t; i < KTOT; i += 384) {
        const float v = y[i];
        s += v;
        q = fmaf(v, v, q);
    }
#pragma unroll
    for (int o = 16; o > 0; o >>= 1) {
        s += __shfl_xor_sync(0xffffffffu, s, o);
        q += __shfl_xor_sync(0xffffffffu, q, o);
    }
    __shared__ float ss[12], qs[12];
    __shared__ float mean_b, rstd_b;
    const int wid = t >> 5, ln = t & 31;
    if (ln == 0) { ss[wid] = s; qs[wid] = q; }
    __syncthreads();
    if (t == 0) {
        float S = 0.f, Q = 0.f;
#pragma unroll
        for (int i = 0; i < 12; ++i) { S += ss[i]; Q += qs[i]; }
        const float mean = S * (1.0f / KTOT);
        const float var  = Q * (1.0f / KTOT) - mean * mean;
        mean_b = mean;
        rstd_b = rsqrtf(var + 1e-5f);
    }
    __syncthreads();
    const float mean = mean_b, rstd = rstd_b;
    for (int i = t; i < KTOT; i += 384)
        O[(size_t)n * KTOT + i] = (y[i] - mean) * rstd;
}

// ---------------------------------------------------------------------------
extern "C" void kernel_launch(void* const* d_in, const int* in_sizes, int n_in,
                              void* d_out, int out_size)
{
    const float* x   = (const float*)d_in[0];
    const float* s2t = (const float*)d_in[1];
    const float* t2s = (const float*)d_in[2];
    const float* s0  = (const float*)d_in[3];
    const float* s1  = (const float*)d_in[4];
    // d_in[5] = s2 : unused by the 4-layer schedule
    const float* t0  = (const float*)d_in[6];
    const float* t1  = (const float*)d_in[7];
    const float* t2  = (const float*)d_in[8];
    float* out = (float*)d_out;

    float *ybuf, *h1, *h2;
    cudaGetSymbolAddress((void**)&ybuf, g_ybuf);
    cudaGetSymbolAddress((void**)&h1,   g_h1);
    cudaGetSymbolAddress((void**)&h2,   g_h2);

    const dim3 eg(KSPLIT, NCG);   // 8 x 96 = 768 CTAs

    // Layer 1: y1 = einsum(x, s2t, t0) -> LN -> h1
    cudaMemsetAsync(ybuf, 0, YSZ * sizeof(float));
    einsum_kernel<false, 6><<<eg, 128>>>(s2t, x, t0, nullptr, nullptr, ybuf);
    ln_kernel<<<NN, 384>>>(ybuf, h1);

    // Layer 2: y2 = x@s1 + einsum(h1, t2s, s0) -> LN -> h2
    matmul_kernel<<<NN * DIM, FEAT>>>(x, s1, ybuf);
    einsum_kernel<false, 6><<<eg, 128>>>(t2s, h1, s0, nullptr, nullptr, ybuf);
    ln_kernel<<<NN, 384>>>(ybuf, h2);

    // Layer 3: y3 = h1@t1 + einsum(x, s2t, t2) + einsum(h2, s2t, t0)
    //          (both s2t einsums fused into ONE pass over W) -> LN -> out
    matmul_kernel<<<NN * DIM, FEAT>>>(h1, t1, ybuf);
    einsum_kernel<true, 5><<<eg, 128>>>(s2t, x, t2, h2, t0, ybuf);
    ln_kernel<<<NN, 384>>>(ybuf, out);
}

// round 9
// speedup vs baseline: 1.3150x; 1.3150x over previous
#include <cuda_runtime.h>
#include <cstddef>

// Problem constants
#define NN    16
#define DIM   32
#define FEAT  192
#define KTOT  (DIM*FEAT)      // 6144
#define YSZ   (NN*DIM*FEAT)   // 98304

// Einsum tiling
#define CPC    4               // c's per CTA (A folded into W scalar)
#define NCG    (FEAT/CPC)      // 48 c-groups
#define KSPLIT 12
#define KCTA   (KTOT/KSPLIT)   // 512
#define NST    (KCTA/32)       // 16 stages of 32 k's
#define KSTRIDE ((size_t)32 * FEAT * DIM)   // W bytes-stride of one 32-k stage (in floats)

// Scratch (no allocations allowed -> device globals)
__device__ float g_ybuf[YSZ];
__device__ float g_h1[YSZ];
__device__ float g_h2[YSZ];

__device__ __forceinline__ void cp16(unsigned dst, const void* src) {
    asm volatile("cp.async.cg.shared.global [%0], [%1], 16;\n" :: "r"(dst), "l"(src));
}
#define CP_COMMIT() asm volatile("cp.async.commit_group;\n" ::: "memory")
#define CP_WAIT1()  asm volatile("cp.async.wait_group 1;\n" ::: "memory")

// ---------------------------------------------------------------------------
// Fused weighted einsum, cp.async double-buffered W pipeline (R7 + reg diet):
//   Y[n, m, c] += sum_k H0[n,k] * A0[k%192, c] * W[k, c, m]   (+ H1/A1 stream)
// W viewed as [KTOT][FEAT][DIM]. Per 32-k stage the CTA stages the 16KB tile
// W[32k][4c][32m] via cp.async (double buffered) and the 2KB h tile via a
// register pipeline one stage ahead. Warp w computes kk = w*8..w*8+7, all
// 16 n, all 4 c. All per-stage addresses are running pointers with
// compile-time strides (no per-stage IMAD chains).
// ---------------------------------------------------------------------------
template<bool TWO_H, int MINB>
__global__ void __launch_bounds__(128, MINB)
einsum_kernel(const float* __restrict__ W,
              const float* __restrict__ H0, const float* __restrict__ A0,
              const float* __restrict__ H1, const float* __restrict__ A1,
              float* __restrict__ Y)
{
    const int ks   = blockIdx.x;           // 0..KSPLIT-1
    const int c0   = blockIdx.y * CPC;     // 0..191 step 4
    const int tid  = threadIdx.x;
    const int w    = tid >> 5;
    const int lane = tid & 31;

    __shared__ __align__(16) float  smw[2][32 * 128];   // W tiles, 32KB
    __shared__ __align__(16) float2 shh [2][32][8];     // h stream0, 4KB
    __shared__ __align__(16) float2 shh2[TWO_H ? 2*32*8 : 8];
    __shared__ float sh_a0[CPC][FEAT];
    __shared__ float sh_a1[TWO_H ? CPC * FEAT : 1];

    // Stage A columns for this CTA's 4 c's.
    for (int i = tid; i < CPC * FEAT; i += 128) {
        const int cc = i / FEAT, f = i - cc * FEAT;
        sh_a0[cc][f] = A0[f * FEAT + c0 + cc];
        if (TWO_H) sh_a1[cc * FEAT + f] = A1[f * FEAT + c0 + cc];
    }

    const int kbase = ks * KCTA;
    const int kk_h  = tid >> 2;            // 0..31 : k-row this thread stages
    const int q     = tid & 3;             // n-quad

    // ---- running pointers (stage strides are compile-time constants) ----
    // copy_w source: thread's chunk j covers k = j*4 + (tid>>5), c16 = tid&31.
    const float* wsrc = W + ((size_t)(kbase + (tid >> 5)) * FEAT + c0) * DIM
                          + (tid & 31) * 4;
    // copy_w dst (16B-chunk smem addresses, fixed per thread per buffer):
    const unsigned wdst0 = (unsigned)__cvta_generic_to_shared(
        &smw[0][(tid >> 5) * 128 + (tid & 31) * 4]);
    const unsigned wdst1 = (unsigned)__cvta_generic_to_shared(
        &smw[1][(tid >> 5) * 128 + (tid & 31) * 4]);
    // h source pointers (advance by 32 floats per stage):
    const float* hsrc0 = H0 + kbase + kk_h;
    const float* hsrc1 = TWO_H ? (H1 + kbase + kk_h) : nullptr;

    auto copy_w = [&](unsigned dst, const float* src) {
#pragma unroll
        for (int j = 0; j < 8; ++j)
            cp16(dst + j * 4 * 512,                 // +4 k-rows = 4*128 floats
                 src + (size_t)j * 4 * FEAT * DIM); // +4 k-rows in W
    };

    float hv[4], hv2[4];
    auto load_h = [&](int soff) {
        const float* hp = hsrc0 + soff * 32;
#pragma unroll
        for (int j = 0; j < 4; ++j) hv[j] = hp[(4 * q + j) * KTOT];
        if (TWO_H) {
            const float* hq = hsrc1 + soff * 32;
#pragma unroll
            for (int j = 0; j < 4; ++j) hv2[j] = hq[(4 * q + j) * KTOT];
        }
    };
    auto store_h = [&](int buf) {
        *reinterpret_cast<float4*>(&shh[buf][kk_h][2 * q]) =
            make_float4(hv[0], hv[1], hv[2], hv[3]);
        if (TWO_H)
            *reinterpret_cast<float4*>(&shh2[(buf * 32 + kk_h) * 8 + 2 * q]) =
                make_float4(hv2[0], hv2[1], hv2[2], hv2[3]);
    };

    unsigned long long acc[CPC][8];
#pragma unroll
    for (int cc = 0; cc < CPC; ++cc)
#pragma unroll
        for (int p = 0; p < 8; ++p) acc[cc][p] = 0ull;

    // ---- pipeline prologue ----
    copy_w(wdst0, wsrc);            CP_COMMIT();
    load_h(0);
    copy_w(wdst1, wsrc + KSTRIDE);  CP_COMMIT();
    store_h(0);
    __syncthreads();
    wsrc += 2 * KSTRIDE;            // next stage to copy = s+2

    const int kk0 = w * 8;
    int fb = kbase % FEAT;

    for (int s = 0; s < NST; ++s) {
        CP_WAIT1();
        __syncthreads();                     // W[s] + h[s] visible to all

        if (s + 1 < NST) load_h(s + 1);      // LDG issue only

        const int   buf  = s & 1;
        const float* wcur = &smw[buf][0];

#pragma unroll
        for (int i = 0; i < 8; ++i) {
            const int kk = kk0 + i;
            const float* wrow = wcur + kk * 128 + lane;
            const float wr0 = wrow[0],  wr1 = wrow[32],
                        wr2 = wrow[64], wr3 = wrow[96];
            const float wr[4] = {wr0, wr1, wr2, wr3};
            const ulonglong2* hr =
                reinterpret_cast<const ulonglong2*>(&shh[buf][kk][0]);
            const ulonglong2 h0 = hr[0], h1 = hr[1], h2 = hr[2], h3 = hr[3];
            ulonglong2 g0, g1, g2, g3;
            if (TWO_H) {
                const ulonglong2* gr = reinterpret_cast<const ulonglong2*>(
                    &shh2[(buf * 32 + kk) * 8]);
                g0 = gr[0]; g1 = gr[1]; g2 = gr[2]; g3 = gr[3];
            }
#pragma unroll
            for (int cc = 0; cc < CPC; ++cc) {
                {
                    const float wv = wr[cc] * sh_a0[cc][fb + kk];
                    unsigned long long wd;
                    asm("mov.b64 %0, {%1, %1};" : "=l"(wd) : "f"(wv));
                    asm("fma.rn.f32x2 %0, %1, %2, %0;" : "+l"(acc[cc][0]) : "l"(h0.x), "l"(wd));
                    asm("fma.rn.f32x2 %0, %1, %2, %0;" : "+l"(acc[cc][1]) : "l"(h0.y), "l"(wd));
                    asm("fma.rn.f32x2 %0, %1, %2, %0;" : "+l"(acc[cc][2]) : "l"(h1.x), "l"(wd));
                    asm("fma.rn.f32x2 %0, %1, %2, %0;" : "+l"(acc[cc][3]) : "l"(h1.y), "l"(wd));
                    asm("fma.rn.f32x2 %0, %1, %2, %0;" : "+l"(acc[cc][4]) : "l"(h2.x), "l"(wd));
                    asm("fma.rn.f32x2 %0, %1, %2, %0;" : "+l"(acc[cc][5]) : "l"(h2.y), "l"(wd));
                    asm("fma.rn.f32x2 %0, %1, %2, %0;" : "+l"(acc[cc][6]) : "l"(h3.x), "l"(wd));
                    asm("fma.rn.f32x2 %0, %1, %2, %0;" : "+l"(acc[cc][7]) : "l"(h3.y), "l"(wd));
                }
                if (TWO_H) {
                    const float wv1 = wr[cc] * sh_a1[cc * FEAT + fb + kk];
                    unsigned long long wd1;
                    asm("mov.b64 %0, {%1, %1};" : "=l"(wd1) : "f"(wv1));
                    asm("fma.rn.f32x2 %0, %1, %2, %0;" : "+l"(acc[cc][0]) : "l"(g0.x), "l"(wd1));
                    asm("fma.rn.f32x2 %0, %1, %2, %0;" : "+l"(acc[cc][1]) : "l"(g0.y), "l"(wd1));
                    asm("fma.rn.f32x2 %0, %1, %2, %0;" : "+l"(acc[cc][2]) : "l"(g1.x), "l"(wd1));
                    asm("fma.rn.f32x2 %0, %1, %2, %0;" : "+l"(acc[cc][3]) : "l"(g1.y), "l"(wd1));
                    asm("fma.rn.f32x2 %0, %1, %2, %0;" : "+l"(acc[cc][4]) : "l"(g2.x), "l"(wd1));
                    asm("fma.rn.f32x2 %0, %1, %2, %0;" : "+l"(acc[cc][5]) : "l"(g2.y), "l"(wd1));
                    asm("fma.rn.f32x2 %0, %1, %2, %0;" : "+l"(acc[cc][6]) : "l"(g3.x), "l"(wd1));
                    asm("fma.rn.f32x2 %0, %1, %2, %0;" : "+l"(acc[cc][7]) : "l"(g3.y), "l"(wd1));
                }
            }
        }

        if (s + 1 < NST) store_h((s + 1) & 1);
        __syncthreads();                     // everyone done with buffer s&1
        if (s + 2 < NST) {
            copy_w((s & 1) ? wdst1 : wdst0, wsrc);
            wsrc += KSTRIDE;
        }
        CP_COMMIT();

        fb += 32; if (fb == FEAT) fb = 0;    // (kbase+s*32)%FEAT, no div
    }

    // ---- cross-warp reduction (W buffer reused), then atomics ----
    unsigned long long* sred = reinterpret_cast<unsigned long long*>(smw);
#pragma unroll
    for (int cc = 0; cc < CPC; ++cc)
#pragma unroll
        for (int p = 0; p < 8; ++p)
            sred[w * 1024 + cc * 256 + p * 32 + lane] = acc[cc][p];
    __syncthreads();

#pragma unroll
    for (int r = 0; r < 8; ++r) {
        const int idx = tid + r * 128;     // (cc, p, m)
        const unsigned long long v0 = sred[idx];
        const unsigned long long v1 = sred[idx + 1024];
        const unsigned long long v2 = sred[idx + 2048];
        const unsigned long long v3 = sred[idx + 3072];
        unsigned long long s01, s23, sm;
        asm("add.rn.f32x2 %0, %1, %2;" : "=l"(s01) : "l"(v0), "l"(v1));
        asm("add.rn.f32x2 %0, %1, %2;" : "=l"(s23) : "l"(v2), "l"(v3));
        asm("add.rn.f32x2 %0, %1, %2;" : "=l"(sm)  : "l"(s01), "l"(s23));
        float lo, hi;
        asm("mov.b64 {%0, %1}, %2;" : "=f"(lo), "=f"(hi) : "l"(sm));
        const int cc = idx >> 8, p = (idx >> 5) & 7, m = idx & 31;
        float* yp = Y + ((size_t)(2 * p) * DIM + m) * FEAT + c0 + cc;
        atomicAdd(yp,                      lo);
        atomicAdd(yp + (size_t)DIM * FEAT, hi);
    }
}

// ---------------------------------------------------------------------------
// Plain transition matmul: Y[row, c] = sum_f H[row, f] * M[f, c]
// Overwrites Y (initializes the layer accumulator); einsum atomicAdds on top.
// ---------------------------------------------------------------------------
__global__ void matmul_kernel(const float* __restrict__ H,
                              const float* __restrict__ M,
                              float* __restrict__ Y)
{
    __shared__ float sh[FEAT];
    const int row = blockIdx.x;
    const int t   = threadIdx.x;
    sh[t] = H[row * FEAT + t];
    __syncthreads();
    float s0 = 0.f, s1 = 0.f, s2 = 0.f, s3 = 0.f;
#pragma unroll 8
    for (int f = 0; f < FEAT; f += 4) {
        s0 = fmaf(sh[f    ], M[(f    ) * FEAT + t], s0);
        s1 = fmaf(sh[f + 1], M[(f + 1) * FEAT + t], s1);
        s2 = fmaf(sh[f + 2], M[(f + 2) * FEAT + t], s2);
        s3 = fmaf(sh[f + 3], M[(f + 3) * FEAT + t], s3);
    }
    Y[row * FEAT + t] = (s0 + s1) + (s2 + s3);
}

// ---------------------------------------------------------------------------
// LayerNorm over last two dims (6144 per n), eps=1e-5, no affine.
// (mean-over-terms division skipped: LN is scale-invariant)
// ---------------------------------------------------------------------------
__global__ void ln_kernel(const float* __restrict__ Y, float* __restrict__ O)
{
    const int n = blockIdx.x;
    const int t = threadIdx.x;
    const float* y = Y + (size_t)n * KTOT;

    float s = 0.f, q = 0.f;
    for (int i = t; i < KTOT; i += 384) {
        const float v = y[i];
        s += v;
        q = fmaf(v, v, q);
    }
#pragma unroll
    for (int o = 16; o > 0; o >>= 1) {
        s += __shfl_xor_sync(0xffffffffu, s, o);
        q += __shfl_xor_sync(0xffffffffu, q, o);
    }
    __shared__ float ss[12], qs[12];
    __shared__ float mean_b, rstd_b;
    const int wid = t >> 5, ln = t & 31;
    if (ln == 0) { ss[wid] = s; qs[wid] = q; }
    __syncthreads();
    if (t == 0) {
        float S = 0.f, Q = 0.f;
#pragma unroll
        for (int i = 0; i < 12; ++i) { S += ss[i]; Q += qs[i]; }
        const float mean = S * (1.0f / KTOT);
        const float var  = Q * (1.0f / KTOT) - mean * mean;
        mean_b = mean;
        rstd_b = rsqrtf(var + 1e-5f);
    }
    __syncthreads();
    const float mean = mean_b, rstd = rstd_b;
    for (int i = t; i < KTOT; i += 384)
        O[(size_t)n * KTOT + i] = (y[i] - mean) * rstd;
}

// ---------------------------------------------------------------------------
extern "C" void kernel_launch(void* const* d_in, const int* in_sizes, int n_in,
                              void* d_out, int out_size)
{
    const float* x   = (const float*)d_in[0];
    const float* s2t = (const float*)d_in[1];
    const float* t2s = (const float*)d_in[2];
    const float* s0  = (const float*)d_in[3];
    const float* s1  = (const float*)d_in[4];
    // d_in[5] = s2 : unused by the 4-layer schedule
    const float* t0  = (const float*)d_in[6];
    const float* t1  = (const float*)d_in[7];
    const float* t2  = (const float*)d_in[8];
    float* out = (float*)d_out;

    float *ybuf, *h1, *h2;
    cudaGetSymbolAddress((void**)&ybuf, g_ybuf);
    cudaGetSymbolAddress((void**)&h1,   g_h1);
    cudaGetSymbolAddress((void**)&h2,   g_h2);

    const dim3 eg(KSPLIT, NCG);   // 12 x 48 = 576 CTAs

    // Layer 1: y1 = einsum(x, s2t, t0) -> LN -> h1
    cudaMemsetAsync(ybuf, 0, YSZ * sizeof(float));
    einsum_kernel<false, 4><<<eg, 128>>>(s2t, x, t0, nullptr, nullptr, ybuf);
    ln_kernel<<<NN, 384>>>(ybuf, h1);

    // Layer 2: y2 = x@s1 + einsum(h1, t2s, s0) -> LN -> h2
    matmul_kernel<<<NN * DIM, FEAT>>>(x, s1, ybuf);
    einsum_kernel<false, 4><<<eg, 128>>>(t2s, h1, s0, nullptr, nullptr, ybuf);
    ln_kernel<<<NN, 384>>>(ybuf, h2);

    // Layer 3: y3 = h1@t1 + einsum(x, s2t, t2) + einsum(h2, s2t, t0)
    //          (both s2t einsums fused into ONE pass over W) -> LN -> out
    matmul_kernel<<<NN * DIM, FEAT>>>(h1, t1, ybuf);
    einsum_kernel<true, 3><<<eg, 128>>>(s2t, x, t2, h2, t0, ybuf);
    ln_kernel<<<NN, 384>>>(ybuf, out);
}